// round 6
// baseline (speedup 1.0000x reference)
#include <cuda_runtime.h>
#include <cstdint>

#define BB 128
#define CC 32
#define LL 4096
#define LT 16           // l positions per CTA
#define BCH 8           // batch rows per chunk
#define NCH 4           // chunks per CTA (32 b per CTA)
#define BSPLIT 4        // b-splits across CTAs
#define THREADS 512     // 16 warps, warp w handles l = l0 + w

#define XS_FLOATS (BCH * LT * CC)     // 4096 floats = 16 KB : x_s[b][l][c] (swizzled)

__device__ __forceinline__ unsigned long long pack_f32x2(float lo, float hi) {
    unsigned long long r;
    asm("mov.b64 %0, {%1, %2};" : "=l"(r) : "r"(__float_as_uint(lo)), "r"(__float_as_uint(hi)));
    return r;
}
__device__ __forceinline__ void unpack_f32x2(unsigned long long v, float& lo, float& hi) {
    unsigned int a, b;
    asm("mov.b64 {%0, %1}, %2;" : "=r"(a), "=r"(b) : "l"(v));
    lo = __uint_as_float(a);
    hi = __uint_as_float(b);
}
__device__ __forceinline__ void fma2(unsigned long long& d, unsigned long long a,
                                     unsigned long long b, unsigned long long c) {
    asm("fma.rn.f32x2 %0, %1, %2, %3;" : "=l"(d) : "l"(a), "l"(b), "l"(c));
}
__device__ __forceinline__ unsigned long long add2(unsigned long long a, unsigned long long b) {
    unsigned long long d;
    asm("add.rn.f32x2 %0, %1, %2;" : "=l"(d) : "l"(a), "l"(b));
    return d;
}

__global__ void __launch_bounds__(THREADS, 2)
dyna_dec_kernel(const float* __restrict__ x, const float* __restrict__ weight,
                const float* __restrict__ bias, float* __restrict__ out) {
    __shared__ __align__(16) float x_s[XS_FLOATS];

    const int tid  = threadIdx.x;
    const int w    = tid >> 5;       // warp index = local l
    const int lane = tid & 31;       // output channel d (compute phase)
    const int l0   = blockIdx.x * LT;
    const int b0   = blockIdx.y * (BCH * NCH);
    const int lg   = l0 + w;

    // ---- Per-warp weight column: W2[p] = {W[lg][2p][lane], W[lg][2p+1][lane]} ----
    unsigned long long W2[CC / 2];
    {
        const float* wp = weight + (size_t)lg * CC * CC + lane;
        #pragma unroll
        for (int p = 0; p < CC / 2; p++) {
            float a = __ldg(wp + (2 * p) * CC);
            float b = __ldg(wp + (2 * p + 1) * CC);
            W2[p] = pack_f32x2(a, b);
        }
    }
    const float bi = __ldg(bias + lg * CC + lane);

    const int swc = (w >> 1) & 6;    // compute-side x_s chunk swizzle for l = w

    float4 pf0, pf1;                 // prefetch registers (2 tasks/thread)

    // ---------- prologue: prefetch chunk 0 ----------
    {
        int t0 = tid,           ls0 = t0 & 3, r0 = t0 >> 2;
        int t1 = THREADS + tid, ls1 = t1 & 3, r1 = t1 >> 2;
        pf0 = *(const float4*)(x + ((size_t)((b0 + (r0 >> 5)) * CC + (r0 & 31))) * LL + l0 + 4 * ls0);
        pf1 = *(const float4*)(x + ((size_t)((b0 + (r1 >> 5)) * CC + (r1 & 31))) * LL + l0 + 4 * ls1);
    }

    for (int ch = 0; ch < NCH; ch++) {
        __syncthreads();  // previous chunk's compute (x_s reads) done

        // ---- stage prefetched chunk into x_s (swizzled, conflict-free STS) ----
        #pragma unroll
        for (int it = 0; it < 2; it++) {
            int t = it * THREADS + tid;
            int lseg = t & 3;
            int r = t >> 2;
            int b = r >> 5, c = r & 31;
            int slot = ((c >> 2) ^ (2 * lseg)) & 7;
            float* dst = x_s + b * (LT * CC) + (4 * lseg) * CC + slot * 4 + (c & 3);
            float4 v = it == 0 ? pf0 : pf1;
            dst[0 * CC] = v.x; dst[1 * CC] = v.y; dst[2 * CC] = v.z; dst[3 * CC] = v.w;
        }

        // ---- prefetch next chunk (LDG latency hidden behind compute) ----
        if (ch + 1 < NCH) {
            int bc = b0 + (ch + 1) * BCH;
            int t0 = tid,           ls0 = t0 & 3, r0 = t0 >> 2;
            int t1 = THREADS + tid, ls1 = t1 & 3, r1 = t1 >> 2;
            pf0 = *(const float4*)(x + ((size_t)((bc + (r0 >> 5)) * CC + (r0 & 31))) * LL + l0 + 4 * ls0);
            pf1 = *(const float4*)(x + ((size_t)((bc + (r1 >> 5)) * CC + (r1 & 31))) * LL + l0 + 4 * ls1);
        }
        __syncthreads();  // x_s ready

        // ---- compute: warp w handles l = l0 + w; lane = d; direct STG out ----
        {
            float* outp = out + (size_t)((b0 + ch * BCH) * CC + lane) * LL + lg;
            #pragma unroll
            for (int b = 0; b < BCH; b++) {
                const char* base = (const char*)(x_s + b * (LT * CC) + w * CC);
                unsigned long long a0 = 0ull, a1 = 0ull, a2 = 0ull, a3 = 0ull;
                #pragma unroll
                for (int u = 0; u < 8; u += 2) {
                    ulonglong2 v0 = *(const ulonglong2*)(base + ((( u      ^ swc) & 7) << 4));
                    ulonglong2 v1 = *(const ulonglong2*)(base + ((((u + 1) ^ swc) & 7) << 4));
                    fma2(a0, v0.x, W2[2 * u + 0], a0);
                    fma2(a1, v0.y, W2[2 * u + 1], a1);
                    fma2(a2, v1.x, W2[2 * u + 2], a2);
                    fma2(a3, v1.y, W2[2 * u + 3], a3);
                }
                unsigned long long s = add2(add2(a0, a1), add2(a2, a3));
                float lo, hi;
                unpack_f32x2(s, lo, hi);
                // scalar STG: lanes scatter across d-lines; the 8 warps sharing
                // this b fill every 32B sector (l0..l0+7 / +8..+15) -> L2 merges.
                outp[(size_t)b * CC * LL] = lo + hi + bi;
            }
        }
    }
}

extern "C" void kernel_launch(void* const* d_in, const int* in_sizes, int n_in,
                              void* d_out, int out_size) {
    const float* x      = (const float*)d_in[0];
    // d_in[1] = px, unused by the reference
    const float* weight = (const float*)d_in[2];
    const float* bias   = (const float*)d_in[3];
    float* out          = (float*)d_out;

    dim3 grid(LL / LT, BSPLIT);   // (256, 4) = 1024 CTAs
    dim3 block(THREADS);
    dyna_dec_kernel<<<grid, block>>>(x, weight, bias, out);
}

// round 7
// speedup vs baseline: 1.4085x; 1.4085x over previous
#include <cuda_runtime.h>
#include <cstdint>

#define BB 128
#define CC 32
#define LL 4096
#define LT 32           // l positions per CTA = one full 128B line of the l-dim
#define BCH 8           // batch rows per chunk
#define NCH 4           // chunks per CTA (32 b per CTA)
#define BSPLIT 4        // b-splits across CTAs
#define THREADS 1024    // 32 warps, warp w handles l = l0 + w

#define XS_FLOATS (BCH * LT * CC)     // 8192 floats = 32 KB
#define OS_PAD 33
#define OS_FLOATS (BCH * CC * OS_PAD) // 8448 floats = 33 KB
#define SMEM_BYTES ((XS_FLOATS + OS_FLOATS) * 4)

__device__ __forceinline__ unsigned long long pack_f32x2(float lo, float hi) {
    unsigned long long r;
    asm("mov.b64 %0, {%1, %2};" : "=l"(r) : "r"(__float_as_uint(lo)), "r"(__float_as_uint(hi)));
    return r;
}
__device__ __forceinline__ void unpack_f32x2(unsigned long long v, float& lo, float& hi) {
    unsigned int a, b;
    asm("mov.b64 {%0, %1}, %2;" : "=r"(a), "=r"(b) : "l"(v));
    lo = __uint_as_float(a);
    hi = __uint_as_float(b);
}
__device__ __forceinline__ void fma2(unsigned long long& d, unsigned long long a,
                                     unsigned long long b, unsigned long long c) {
    asm("fma.rn.f32x2 %0, %1, %2, %3;" : "=l"(d) : "l"(a), "l"(b), "l"(c));
}
__device__ __forceinline__ unsigned long long add2(unsigned long long a, unsigned long long b) {
    unsigned long long d;
    asm("add.rn.f32x2 %0, %1, %2;" : "=l"(d) : "l"(a), "l"(b));
    return d;
}

__global__ void __launch_bounds__(THREADS, 1)
dyna_dec_kernel(const float* __restrict__ x, const float* __restrict__ weight,
                const float* __restrict__ bias, float* __restrict__ out) {
    extern __shared__ float smem[];
    float* x_s = smem;              // [BCH][LT][CC], c rotated by (l&28)
    float* o_s = smem + XS_FLOATS;  // [BCH*CC rows][OS_PAD]

    const int tid  = threadIdx.x;
    const int w    = tid >> 5;       // warp index = local l (0..31)
    const int lane = tid & 31;       // output channel d (compute phase)
    const int b0   = blockIdx.x * (BCH * NCH);   // b-split major -> weight L2 reuse
    const int l0   = blockIdx.y * LT;
    const int lg   = l0 + w;

    // ---- Per-warp weight column: W2[p] = {W[lg][2p][lane], W[lg][2p+1][lane]} ----
    unsigned long long W2[CC / 2];
    {
        const float* wp = weight + (size_t)lg * CC * CC + lane;
        #pragma unroll
        for (int p = 0; p < CC / 2; p++) {
            float a = __ldg(wp + (2 * p) * CC);      // 128B coalesced per load
            float b = __ldg(wp + (2 * p + 1) * CC);
            W2[p] = pack_f32x2(a, b);
        }
    }
    const float bi  = __ldg(bias + lg * CC + lane);
    const int   rot = (w >> 2) & 7;  // compute-side 16B-chunk rotation for l = w

    float4 pf0, pf1;                 // prefetch registers (2 float4-tasks/thread)

    // ---------- prologue: prefetch chunk 0 (full 128B lines) ----------
    {
        int i0 = tid,           s0 = i0 & 7, r0 = i0 >> 3;
        int i1 = THREADS + tid, s1 = i1 & 7, r1 = i1 >> 3;
        pf0 = *(const float4*)(x + ((size_t)((b0 + (r0 >> 5)) * CC + (r0 & 31))) * LL + l0 + 4 * s0);
        pf1 = *(const float4*)(x + ((size_t)((b0 + (r1 >> 5)) * CC + (r1 & 31))) * LL + l0 + 4 * s1);
    }

    for (int ch = 0; ch < NCH; ch++) {
        __syncthreads();  // previous chunk's compute (x_s reads) done

        // ---- stage prefetched chunk into x_s (rotated c -> conflict-free STS) ----
        #pragma unroll
        for (int it = 0; it < 2; it++) {
            int i = it * THREADS + tid;
            int s = i & 7;          // l-segment: l = 4s..4s+3
            int r = i >> 3;
            int b = r >> 5, c = r & 31;
            int cr = (c + 4 * s) & 31;           // rotation = l & 28 = 4s
            float* dst = x_s + b * (LT * CC) + (4 * s) * CC + cr;
            float4 v = it == 0 ? pf0 : pf1;
            dst[0 * CC] = v.x; dst[1 * CC] = v.y; dst[2 * CC] = v.z; dst[3 * CC] = v.w;
        }

        // ---- prefetch next chunk (LDG latency hidden behind compute) ----
        if (ch + 1 < NCH) {
            int bc = b0 + (ch + 1) * BCH;
            int i0 = tid,           s0 = i0 & 7, r0 = i0 >> 3;
            int i1 = THREADS + tid, s1 = i1 & 7, r1 = i1 >> 3;
            pf0 = *(const float4*)(x + ((size_t)((bc + (r0 >> 5)) * CC + (r0 & 31))) * LL + l0 + 4 * s0);
            pf1 = *(const float4*)(x + ((size_t)((bc + (r1 >> 5)) * CC + (r1 & 31))) * LL + l0 + 4 * s1);
        }
        __syncthreads();  // x_s ready

        // ---- compute: warp w = l; lane = d; 4 accumulators ----
        #pragma unroll
        for (int b = 0; b < BCH; b++) {
            const float* basef = x_s + b * (LT * CC) + w * CC;
            unsigned long long a0 = 0ull, a1 = 0ull, a2 = 0ull, a3 = 0ull;
            #pragma unroll
            for (int u = 0; u < 8; u += 2) {
                ulonglong2 v0 = *(const ulonglong2*)(basef + (((u     + rot) & 7) << 2));
                ulonglong2 v1 = *(const ulonglong2*)(basef + (((u + 1 + rot) & 7) << 2));
                fma2(a0, v0.x, W2[2 * u + 0], a0);
                fma2(a1, v0.y, W2[2 * u + 1], a1);
                fma2(a2, v1.x, W2[2 * u + 2], a2);
                fma2(a3, v1.y, W2[2 * u + 3], a3);
            }
            unsigned long long s = add2(add2(a0, a1), add2(a2, a3));
            float lo, hi;
            unpack_f32x2(s, lo, hi);
            // bank = (lane + w) mod 32 across lanes: conflict-free
            o_s[(b * CC + lane) * OS_PAD + w] = lo + hi + bi;
        }
        __syncthreads();  // o_s ready

        // ---- output pass: gather rows from o_s, full-line STG.128 ----
        #pragma unroll
        for (int it = 0; it < 2; it++) {
            int i = it * THREADS + tid;
            int s = i & 7;
            int r = i >> 3;                 // row = b*32 + d
            int b = r >> 5, d = r & 31;
            const float* src = o_s + r * OS_PAD + 4 * s;   // bank r+4s+j: conflict-free
            float4 v;
            v.x = src[0]; v.y = src[1]; v.z = src[2]; v.w = src[3];
            *(float4*)(out + ((size_t)((b0 + ch * BCH + b) * CC + d)) * LL + l0 + 4 * s) = v;
        }
    }
}

extern "C" void kernel_launch(void* const* d_in, const int* in_sizes, int n_in,
                              void* d_out, int out_size) {
    const float* x      = (const float*)d_in[0];
    // d_in[1] = px, unused by the reference
    const float* weight = (const float*)d_in[2];
    const float* bias   = (const float*)d_in[3];
    float* out          = (float*)d_out;

    cudaFuncSetAttribute(dyna_dec_kernel, cudaFuncAttributeMaxDynamicSharedMemorySize,
                         SMEM_BYTES);

    dim3 grid(BSPLIT, LL / LT);   // (4, 128): weight-sharing siblings wave-adjacent
    dim3 block(THREADS);
    dyna_dec_kernel<<<grid, block, SMEM_BYTES>>>(x, weight, bias, out);
}

// round 8
// speedup vs baseline: 1.7449x; 1.2388x over previous
#include <cuda_runtime.h>
#include <cstdint>

#define BB 128
#define CC 32
#define LL 4096
#define LT 16           // l positions per CTA
#define BCH 8           // batch rows per chunk
#define NCH 4           // chunks per CTA (32 b per CTA)
#define BSPLIT 4        // b-splits across CTAs
#define THREADS 512     // 16 warps, warp w handles l = l0 + w

#define XS_FLOATS (BCH * LT * CC)     // 4096 floats = 16 KB
#define OS_PAD 17
#define OS_FLOATS (BCH * CC * OS_PAD) // 4352 floats = 17 KB

__device__ __forceinline__ unsigned long long pack_f32x2(float lo, float hi) {
    unsigned long long r;
    asm("mov.b64 %0, {%1, %2};" : "=l"(r) : "r"(__float_as_uint(lo)), "r"(__float_as_uint(hi)));
    return r;
}
__device__ __forceinline__ void unpack_f32x2(unsigned long long v, float& lo, float& hi) {
    unsigned int a, b;
    asm("mov.b64 {%0, %1}, %2;" : "=r"(a), "=r"(b) : "l"(v));
    lo = __uint_as_float(a);
    hi = __uint_as_float(b);
}
__device__ __forceinline__ void fma2(unsigned long long& d, unsigned long long a,
                                     unsigned long long b, unsigned long long c) {
    asm("fma.rn.f32x2 %0, %1, %2, %3;" : "=l"(d) : "l"(a), "l"(b), "l"(c));
}
__device__ __forceinline__ unsigned long long add2(unsigned long long a, unsigned long long b) {
    unsigned long long d;
    asm("add.rn.f32x2 %0, %1, %2;" : "=l"(d) : "l"(a), "l"(b));
    return d;
}

__global__ void __launch_bounds__(THREADS, 2)
dyna_dec_kernel(const float* __restrict__ x, const float* __restrict__ weight,
                const float* __restrict__ bias, float* __restrict__ out) {
    __shared__ __align__(16) float x_s[XS_FLOATS];
    __shared__ __align__(16) float o_s[OS_FLOATS];

    const int tid  = threadIdx.x;
    const int w    = tid >> 5;       // warp index = local l
    const int lane = tid & 31;       // output channel d (compute phase)
    const int b0   = blockIdx.x * (BCH * NCH);   // b-split minor -> weight L2 reuse
    const int l0   = blockIdx.y * LT;
    const int lg   = l0 + w;

    // ---- Per-warp weight column: W2[p] = {W[lg][2p][lane], W[lg][2p+1][lane]} ----
    unsigned long long W2[CC / 2];
    {
        const float* wp = weight + (size_t)lg * CC * CC + lane;
        #pragma unroll
        for (int p = 0; p < CC / 2; p++) {
            float a = __ldg(wp + (2 * p) * CC);
            float b = __ldg(wp + (2 * p + 1) * CC);
            W2[p] = pack_f32x2(a, b);
        }
    }
    const float bi = __ldg(bias + lg * CC + lane);

    const int swc = (w >> 1) & 6;    // compute-side x_s chunk swizzle for l = w
    const int seg = w >> 2, j = w & 3;

    float4 pf0, pf1;                 // prefetch registers (2 tasks/thread)

    // ---------- prologue: prefetch chunk 0 ----------
    {
        int t0 = tid,           ls0 = t0 & 3, r0 = t0 >> 2;
        int t1 = THREADS + tid, ls1 = t1 & 3, r1 = t1 >> 2;
        pf0 = *(const float4*)(x + ((size_t)((b0 + (r0 >> 5)) * CC + (r0 & 31))) * LL + l0 + 4 * ls0);
        pf1 = *(const float4*)(x + ((size_t)((b0 + (r1 >> 5)) * CC + (r1 & 31))) * LL + l0 + 4 * ls1);
    }

    for (int ch = 0; ch < NCH; ch++) {
        // ---- stage prefetched chunk into x_s (swizzled, conflict-free STS) ----
        // Safe without a leading sync: the sync after compute(ch-1) guarantees
        // all x_s reads of the previous chunk completed before the out-pass,
        // and stage touches only x_s while out-pass touches only o_s.
        #pragma unroll
        for (int it = 0; it < 2; it++) {
            int t = it * THREADS + tid;
            int lseg = t & 3;
            int r = t >> 2;
            int b = r >> 5, c = r & 31;
            int slot = ((c >> 2) ^ (2 * lseg)) & 7;
            float* dst = x_s + b * (LT * CC) + (4 * lseg) * CC + slot * 4 + (c & 3);
            float4 v = it == 0 ? pf0 : pf1;
            dst[0 * CC] = v.x; dst[1 * CC] = v.y; dst[2 * CC] = v.z; dst[3 * CC] = v.w;
        }

        // ---- prefetch next chunk (LDG latency hidden behind compute) ----
        if (ch + 1 < NCH) {
            int bc = b0 + (ch + 1) * BCH;
            int t0 = tid,           ls0 = t0 & 3, r0 = t0 >> 2;
            int t1 = THREADS + tid, ls1 = t1 & 3, r1 = t1 >> 2;
            pf0 = *(const float4*)(x + ((size_t)((bc + (r0 >> 5)) * CC + (r0 & 31))) * LL + l0 + 4 * ls0);
            pf1 = *(const float4*)(x + ((size_t)((bc + (r1 >> 5)) * CC + (r1 & 31))) * LL + l0 + 4 * ls1);
        }
        __syncthreads();  // x_s ready; also fences out-pass(ch-1) reads of o_s

        // ---- compute: warp w handles l = l0 + w; lane = d; 4 accumulators ----
        #pragma unroll
        for (int b = 0; b < BCH; b++) {
            const char* base = (const char*)(x_s + b * (LT * CC) + w * CC);
            unsigned long long a0 = 0ull, a1 = 0ull, a2 = 0ull, a3 = 0ull;
            #pragma unroll
            for (int u = 0; u < 8; u += 2) {
                ulonglong2 v0 = *(const ulonglong2*)(base + ((( u      ^ swc) & 7) << 4));
                ulonglong2 v1 = *(const ulonglong2*)(base + ((((u + 1) ^ swc) & 7) << 4));
                fma2(a0, v0.x, W2[2 * u + 0], a0);
                fma2(a1, v0.y, W2[2 * u + 1], a1);
                fma2(a2, v1.x, W2[2 * u + 2], a2);
                fma2(a3, v1.y, W2[2 * u + 3], a3);
            }
            unsigned long long s = add2(add2(a0, a1), add2(a2, a3));
            float lo, hi;
            unpack_f32x2(s, lo, hi);
            int row = b * CC + lane;
            int segp = (seg + ((row >> 1) & 2)) & 3;          // additive seg swizzle
            o_s[row * OS_PAD + 4 * segp + j] = lo + hi + bi;  // conflict-free STS
        }
        __syncthreads();  // o_s ready; also fences compute's x_s reads for next stage

        // ---- output pass: gather rows from o_s, vectorized STG ----
        #pragma unroll
        for (int it = 0; it < 2; it++) {
            int t = it * THREADS + tid;
            int s = t & 3;
            int r = t >> 2;                 // row = b*32 + d
            int b = r >> 5, d = r & 31;
            int segp = (s + ((r >> 1) & 2)) & 3;
            const float* src = o_s + r * OS_PAD + 4 * segp;
            float4 v;
            v.x = src[0]; v.y = src[1]; v.z = src[2]; v.w = src[3];
            *(float4*)(out + ((size_t)((b0 + ch * BCH + b) * CC + d)) * LL + l0 + 4 * s) = v;
        }
    }
}

extern "C" void kernel_launch(void* const* d_in, const int* in_sizes, int n_in,
                              void* d_out, int out_size) {
    const float* x      = (const float*)d_in[0];
    // d_in[1] = px, unused by the reference
    const float* weight = (const float*)d_in[2];
    const float* bias   = (const float*)d_in[3];
    float* out          = (float*)d_out;

    dim3 grid(BSPLIT, LL / LT);   // (4, 256): weight-sharing siblings wave-adjacent
    dim3 block(THREADS);
    dyna_dec_kernel<<<grid, block>>>(x, weight, bias, out);
}